// round 16
// baseline (speedup 1.0000x reference)
#include <cuda_runtime.h>
#include <cuda_fp16.h>
#include <cstdint>

// ---------------- problem dims ----------------
#define DIM_M 8192
#define DIM_N 16384
#define DIM_K 4096

#define BM 256
#define BN 128
#define BK 128
#define NSTAGE 2
#define KT2 (DIM_K / BK)     // 32 chunks
#define MT2 (DIM_M / BM)     // 32
#define NT2 (DIM_N / BN)     // 128
#define GM 16                // supertile: m-tiles per group

#define STAGE_BYTES ((BM * BK + BN * BK) * 2)   // A 64K + B 32K = 98304
#define MBAR_OFF (NSTAGE * STAGE_BYTES)         // 196608
#define SMEM_TOTAL (MBAR_OFF + 128)             // + barrier block

// ---------------- device scratch (no allocs allowed) ----------------
__device__ __align__(1024) __half g_x_h[(size_t)DIM_M * DIM_K];   // 64 MB
__device__ __align__(1024) __half g_w_h[(size_t)DIM_N * DIM_K];   // 128 MB

// ---------------- PTX helpers (plain-compute_103-safe, all sm_80-era) ----------------
__device__ __forceinline__ uint32_t smem_u32(const void* p) {
    uint32_t a;
    asm("{ .reg .u64 t; cvta.to.shared.u64 t, %1; cvt.u32.u64 %0, t; }" : "=r"(a) : "l"(p));
    return a;
}

__device__ __forceinline__ void cp_async16(uint32_t saddr, const void* gaddr) {
    asm volatile("cp.async.cg.shared.global [%0], [%1], 16;" :: "r"(saddr), "l"(gaddr) : "memory");
}

#define MBAR_INIT(addr, cnt) \
    asm volatile("mbarrier.init.shared.b64 [%0], %1;" :: "r"(addr), "r"(cnt) : "memory")

#define MBAR_ARRIVE(addr) \
    asm volatile("mbarrier.arrive.shared.b64 _, [%0];" :: "r"(addr) : "memory")

// async arrive when all of this thread's prior cp.asyncs complete (.noinc: counts
// against the initialized expected count)
#define CPASYNC_MBAR_ARRIVE(addr) \
    asm volatile("cp.async.mbarrier.arrive.noinc.shared.b64 [%0];" :: "r"(addr) : "memory")

// plain polling try_wait (R13-proven; no suspend hint — waits usually pass fast-path)
#define MBAR_WAIT(addr, parity) do {                                                    \
    uint32_t _m = (addr), _p = (parity), _d;                                            \
    asm volatile(                                                                       \
        "{\n\t.reg .pred p;\n\t"                                                        \
        "mbarrier.try_wait.parity.shared.b64 p, [%1], %2;\n\t"                          \
        "selp.b32 %0, 1, 0, p;\n\t}"                                                    \
        : "=r"(_d) : "r"(_m), "r"(_p) : "memory");                                      \
    if (!_d) {                                                                          \
        asm volatile(                                                                   \
            "{\n\t.reg .pred P1;\n\t"                                                   \
            "WL_%=:\n\t"                                                                \
            "mbarrier.try_wait.parity.shared.b64 P1, [%0], %1;\n\t"                     \
            "@P1 bra.uni WD_%=;\n\t"                                                    \
            "bra.uni WL_%=;\n\t"                                                        \
            "WD_%=:\n\t}"                                                               \
            :: "r"(_m), "r"(_p) : "memory");                                            \
    }                                                                                   \
} while (0)

#define LDMATRIX_X4(r0, r1, r2, r3, addr)                                              \
    asm volatile("ldmatrix.sync.aligned.m8n8.x4.shared.b16 {%0,%1,%2,%3}, [%4];"        \
                 : "=r"(r0), "=r"(r1), "=r"(r2), "=r"(r3) : "r"(addr))

#define MMA_16816(c, a, b)                                                             \
    asm volatile("mma.sync.aligned.m16n8k16.row.col.f32.f16.f16.f32 "                  \
                 "{%0,%1,%2,%3}, {%4,%5,%6,%7}, {%8,%9}, {%0,%1,%2,%3};"               \
                 : "+f"((c)[0]), "+f"((c)[1]), "+f"((c)[2]), "+f"((c)[3])              \
                 : "r"((a)[0]), "r"((a)[1]), "r"((a)[2]), "r"((a)[3]),                 \
                   "r"((b)[0]), "r"((b)[1]))

// ---------------- merged conversion kernel (proven config) ----------------
__global__ void conv_all_f16(const float* __restrict__ x, const float* __restrict__ w,
                             const float* __restrict__ scale,
                             __half* __restrict__ xh, __half* __restrict__ wh,
                             int n8x, int n8tot) {
    const float s = scale[0];
    for (int i = blockIdx.x * blockDim.x + threadIdx.x; i < n8tot; i += gridDim.x * blockDim.x) {
        union { __half h[8]; uint4 u; } H;
        if (i < n8x) {
            float4 v0 = reinterpret_cast<const float4*>(x)[2 * (size_t)i];
            float4 v1 = reinterpret_cast<const float4*>(x)[2 * (size_t)i + 1];
            H.h[0] = __float2half(v0.x * s); H.h[1] = __float2half(v0.y * s);
            H.h[2] = __float2half(v0.z * s); H.h[3] = __float2half(v0.w * s);
            H.h[4] = __float2half(v1.x * s); H.h[5] = __float2half(v1.y * s);
            H.h[6] = __float2half(v1.z * s); H.h[7] = __float2half(v1.w * s);
            reinterpret_cast<uint4*>(xh)[i] = H.u;
        } else {
            size_t j = (size_t)(i - n8x);
            float4 v0 = reinterpret_cast<const float4*>(w)[2 * j];
            float4 v1 = reinterpret_cast<const float4*>(w)[2 * j + 1];
            H.h[0] = __float2half(v0.x); H.h[1] = __float2half(v0.y);
            H.h[2] = __float2half(v0.z); H.h[3] = __float2half(v0.w);
            H.h[4] = __float2half(v1.x); H.h[5] = __float2half(v1.y);
            H.h[6] = __float2half(v1.z); H.h[7] = __float2half(v1.w);
            reinterpret_cast<uint4*>(wh)[j] = H.u;
        }
    }
}

// ---------------- main GEMM kernel: mbarrier pipeline, 2 stages of BK=128 ----------------
// smem row = 128 fp16 = 256B = 16 chunks of 16B; physical chunk = c ^ (row & 7)
__global__ void __launch_bounds__(256, 1) hmma_gemm(
    const __half* __restrict__ Ah,   // [M, K] fp16, pre-scaled
    const __half* __restrict__ Bh,   // [N, K] fp16 (W)
    const float* __restrict__ bias,  // [N]
    float* __restrict__ out)         // [M, N]
{
    extern __shared__ char smem[];
    const uint32_t sb = smem_u32(smem);
    const int tid = threadIdx.x;
    const int wid = tid >> 5;
    const int lane = tid & 31;
    const int warp_m = wid & 3;   // 0..3 -> 64-row slabs
    const int warp_n = wid >> 2;  // 0..1 -> 64-col slabs

    const uint32_t mb = sb + MBAR_OFF;        // full[s] at +16*s, empty[s] at +64+16*s
#define FULL_B(s)  (mb + 16 * (s))
#define EMPTY_B(s) (mb + 64 + 16 * (s))

    // supertile raster: GM m-tiles fastest, then n, then group
    const int bid = blockIdx.x;
    const int mt = (bid / (GM * NT2)) * GM + (bid % GM);
    const int nt = (bid / GM) % NT2;
    const int m0 = mt * BM;
    const int n0 = nt * BN;

    // per-thread loads for one BK=128 chunk: A 16 + B 8 = 24 cp.async
    auto load_chunk = [&](int s, int kt) {
        const uint32_t sA = sb + s * STAGE_BYTES;
        const uint32_t sB = sA + BM * BK * 2;
        const __half* gA = Ah + (size_t)m0 * DIM_K + (size_t)kt * BK;
        const __half* gB = Bh + (size_t)n0 * DIM_K + (size_t)kt * BK;
#pragma unroll
        for (int i = 0; i < 16; i++) {                // A: 4096 16B-chunks
            int ch = i * 256 + tid;
            int row = ch >> 4, c = ch & 15;
            cp_async16(sA + row * 256 + ((c ^ (row & 7)) << 4),
                       gA + (size_t)row * DIM_K + c * 8);
        }
#pragma unroll
        for (int i = 0; i < 8; i++) {                 // B: 2048 16B-chunks
            int ch = i * 256 + tid;
            int row = ch >> 4, c = ch & 15;
            cp_async16(sB + row * 256 + ((c ^ (row & 7)) << 4),
                       gB + (size_t)row * DIM_K + c * 8);
        }
    };

    // init barriers: full counts all 256 threads' cp.async-arrives;
    // empty counts 8 warp-elected arrives
    if (tid == 0) {
#pragma unroll
        for (int s = 0; s < NSTAGE; s++) {
            MBAR_INIT(FULL_B(s), 256);
            MBAR_INIT(EMPTY_B(s), 8);
        }
    }
    __syncthreads();   // once, for init visibility

    // prologue: fill stage 0 (chunk 0)
    load_chunk(0, 0);
    CPASYNC_MBAR_ARRIVE(FULL_B(0));

    float acc[4][8][4];
#pragma unroll
    for (int i = 0; i < 4; i++)
#pragma unroll
        for (int j = 0; j < 8; j++)
#pragma unroll
            for (int q = 0; q < 4; q++) acc[i][j][q] = 0.0f;

    for (int kt = 0; kt < KT2; kt++) {
        const int s = kt & 1;
        MBAR_WAIT(FULL_B(s), (kt >> 1) & 1);

        // produce chunk kt+1 into the other stage BEFORE computing, so its
        // cp.asyncs are in flight during this whole chunk's MMAs
        const int cp = kt + 1;
        if (cp < KT2) {
            const int sp = cp & 1;               // == s ^ 1
            if (cp >= NSTAGE) MBAR_WAIT(EMPTY_B(sp), ((cp >> 1) + 1) & 1);
            load_chunk(sp, cp);
            CPASYNC_MBAR_ARRIVE(FULL_B(sp));
        }

        const uint32_t sA = sb + s * STAGE_BYTES;
        const uint32_t sB = sA + BM * BK * 2;

#pragma unroll
        for (int ks = 0; ks < 8; ks++) {   // 8 x k16 per BK=128 chunk
            uint32_t a[4][4];
#pragma unroll
            for (int mi = 0; mi < 4; mi++) {
                int row = warp_m * 64 + mi * 16 + (lane & 15);
                int chunk = ks * 2 + (lane >> 4);
                uint32_t addr = sA + row * 256 + ((chunk ^ (row & 7)) << 4);
                LDMATRIX_X4(a[mi][0], a[mi][1], a[mi][2], a[mi][3], addr);
            }
            uint32_t b[8][2];
#pragma unroll
            for (int p = 0; p < 4; p++) {
                int lane8 = lane & 7;
                int g = lane >> 3;
                int rowb = warp_n * 64 + p * 16 + ((g & 2) ? 8 : 0) + lane8;
                int chunk = ks * 2 + (g & 1);
                uint32_t addr = sB + rowb * 256 + ((chunk ^ (rowb & 7)) << 4);
                LDMATRIX_X4(b[2 * p][0], b[2 * p][1], b[2 * p + 1][0], b[2 * p + 1][1], addr);
            }
#pragma unroll
            for (int mi = 0; mi < 4; mi++)
#pragma unroll
                for (int ni = 0; ni < 8; ni++)
                    MMA_16816(acc[mi][ni], a[mi], b[ni]);
        }

        // done reading stage s: warp-elected arrive
        __syncwarp();
        if (lane == 0) MBAR_ARRIVE(EMPTY_B(s));
    }

    // -------- epilogue: direct register -> gmem (float2), + bias --------
    float2 bv[8];
#pragma unroll
    for (int ni = 0; ni < 8; ni++) {
        int col = n0 + warp_n * 64 + ni * 8 + 2 * (lane & 3);
        bv[ni] = *reinterpret_cast<const float2*>(bias + col);
    }
#pragma unroll
    for (int mi = 0; mi < 4; mi++) {
        size_t r0 = (size_t)(m0 + warp_m * 64 + mi * 16 + (lane >> 2));
        size_t r1 = r0 + 8;
#pragma unroll
        for (int ni = 0; ni < 8; ni++) {
            int col = n0 + warp_n * 64 + ni * 8 + 2 * (lane & 3);
            float2 v0 = make_float2(acc[mi][ni][0] + bv[ni].x, acc[mi][ni][1] + bv[ni].y);
            float2 v1 = make_float2(acc[mi][ni][2] + bv[ni].x, acc[mi][ni][3] + bv[ni].y);
            *reinterpret_cast<float2*>(out + r0 * DIM_N + col) = v0;
            *reinterpret_cast<float2*>(out + r1 * DIM_N + col) = v1;
        }
    }
}

// ---------------- host launch ----------------
extern "C" void kernel_launch(void* const* d_in, const int* in_sizes, int n_in,
                              void* d_out, int out_size) {
    const float* x     = (const float*)d_in[0];
    const float* w     = (const float*)d_in[1];
    const float* scale = (const float*)d_in[2];
    const float* bias  = (const float*)d_in[3];
    float* out = (float*)d_out;

    void *p_xh = nullptr, *p_wh = nullptr;
    cudaGetSymbolAddress(&p_xh, g_x_h);
    cudaGetSymbolAddress(&p_wh, g_w_h);

    const int n8x = DIM_M * DIM_K / 8;
    const int n8w = (int)((size_t)DIM_N * DIM_K / 8);
    const int n8tot = n8x + n8w;
    const int cta = 256;
    int blocks = (n8tot + cta * 4 - 1) / (cta * 4);
    conv_all_f16<<<blocks, cta>>>(x, w, scale, (__half*)p_xh, (__half*)p_wh, n8x, n8tot);

    cudaFuncSetAttribute(hmma_gemm, cudaFuncAttributeMaxDynamicSharedMemorySize, SMEM_TOTAL);
    hmma_gemm<<<MT2 * NT2, 256, SMEM_TOTAL>>>((const __half*)p_xh, (const __half*)p_wh, bias, out);
}

// round 17
// speedup vs baseline: 1.0744x; 1.0744x over previous
#include <cuda_runtime.h>
#include <cuda.h>
#include <cuda_fp16.h>
#include <cstdint>

// ---------------- problem dims ----------------
#define DIM_M 8192
#define DIM_N 16384
#define DIM_K 4096

#define BM 256
#define BN 128
#define BK 64
#define NSTAGE 4
#define KT2 (DIM_K / BK)     // 64 chunks
#define MT2 (DIM_M / BM)     // 32
#define NT2 (DIM_N / BN)     // 128
#define GM 16                // supertile: m-tiles per group

#define A_BYTES (BM * BK * 2)                   // 32768
#define STAGE_BYTES ((BM * BK + BN * BK) * 2)   // A 32K + B 16K = 49152
#define MBAR_OFF (NSTAGE * STAGE_BYTES)         // 196608
#define SMEM_TOTAL (MBAR_OFF + 128)

// ---------------- device scratch (no allocs allowed) ----------------
__device__ __align__(1024) __half g_x_h[(size_t)DIM_M * DIM_K];   // 64 MB
__device__ __align__(1024) __half g_w_h[(size_t)DIM_N * DIM_K];   // 128 MB

// ---------------- PTX helpers (plain-compute_103-safe: sm_80 mbarrier + sm_90 TMA) ----------------
__device__ __forceinline__ uint32_t smem_u32(const void* p) {
    uint32_t a;
    asm("{ .reg .u64 t; cvta.to.shared.u64 t, %1; cvt.u32.u64 %0, t; }" : "=r"(a) : "l"(p));
    return a;
}

#define MBAR_INIT(addr, cnt) \
    asm volatile("mbarrier.init.shared.b64 [%0], %1;" :: "r"(addr), "r"(cnt) : "memory")

#define MBAR_ARRIVE(addr) \
    asm volatile("mbarrier.arrive.shared.b64 _, [%0];" :: "r"(addr) : "memory")

#define MBAR_EXPECT_TX(addr, bytes) \
    asm volatile("mbarrier.arrive.expect_tx.shared.b64 _, [%0], %1;" \
        :: "r"(addr), "r"((uint32_t)(bytes)) : "memory")

#define TMA_LOAD_2D(smem_addr, map_ptr, cx, cy, mbar)                                   \
    asm volatile(                                                                       \
        "cp.async.bulk.tensor.2d.shared::cta.global.tile.mbarrier::complete_tx::bytes " \
        "[%0], [%1, {%2, %3}], [%4];"                                                   \
        :: "r"((uint32_t)(smem_addr)), "l"(map_ptr), "r"((int)(cx)), "r"((int)(cy)),    \
           "r"((uint32_t)(mbar)) : "memory")

// plain polling try_wait (R13-proven)
#define MBAR_WAIT(addr, parity) do {                                                    \
    uint32_t _m = (addr), _p = (parity), _d;                                            \
    asm volatile(                                                                       \
        "{\n\t.reg .pred p;\n\t"                                                        \
        "mbarrier.try_wait.parity.shared.b64 p, [%1], %2;\n\t"                          \
        "selp.b32 %0, 1, 0, p;\n\t}"                                                    \
        : "=r"(_d) : "r"(_m), "r"(_p) : "memory");                                      \
    if (!_d) {                                                                          \
        asm volatile(                                                                   \
            "{\n\t.reg .pred P1;\n\t"                                                   \
            "WL_%=:\n\t"                                                                \
            "mbarrier.try_wait.parity.shared.b64 P1, [%0], %1;\n\t"                     \
            "@P1 bra.uni WD_%=;\n\t"                                                    \
            "bra.uni WL_%=;\n\t"                                                        \
            "WD_%=:\n\t}"                                                               \
            :: "r"(_m), "r"(_p) : "memory");                                            \
    }                                                                                   \
} while (0)

#define LDMATRIX_X4(r0, r1, r2, r3, addr)                                              \
    asm volatile("ldmatrix.sync.aligned.m8n8.x4.shared.b16 {%0,%1,%2,%3}, [%4];"        \
                 : "=r"(r0), "=r"(r1), "=r"(r2), "=r"(r3) : "r"(addr))

#define MMA_16816(c, a, b)                                                             \
    asm volatile("mma.sync.aligned.m16n8k16.row.col.f32.f16.f16.f32 "                  \
                 "{%0,%1,%2,%3}, {%4,%5,%6,%7}, {%8,%9}, {%0,%1,%2,%3};"               \
                 : "+f"((c)[0]), "+f"((c)[1]), "+f"((c)[2]), "+f"((c)[3])              \
                 : "r"((a)[0]), "r"((a)[1]), "r"((a)[2]), "r"((a)[3]),                 \
                   "r"((b)[0]), "r"((b)[1]))

// ---------------- merged conversion kernel (proven config) ----------------
__global__ void conv_all_f16(const float* __restrict__ x, const float* __restrict__ w,
                             const float* __restrict__ scale,
                             __half* __restrict__ xh, __half* __restrict__ wh,
                             int n8x, int n8tot) {
    const float s = scale[0];
    for (int i = blockIdx.x * blockDim.x + threadIdx.x; i < n8tot; i += gridDim.x * blockDim.x) {
        union { __half h[8]; uint4 u; } H;
        if (i < n8x) {
            float4 v0 = reinterpret_cast<const float4*>(x)[2 * (size_t)i];
            float4 v1 = reinterpret_cast<const float4*>(x)[2 * (size_t)i + 1];
            H.h[0] = __float2half(v0.x * s); H.h[1] = __float2half(v0.y * s);
            H.h[2] = __float2half(v0.z * s); H.h[3] = __float2half(v0.w * s);
            H.h[4] = __float2half(v1.x * s); H.h[5] = __float2half(v1.y * s);
            H.h[6] = __float2half(v1.z * s); H.h[7] = __float2half(v1.w * s);
            reinterpret_cast<uint4*>(xh)[i] = H.u;
        } else {
            size_t j = (size_t)(i - n8x);
            float4 v0 = reinterpret_cast<const float4*>(w)[2 * j];
            float4 v1 = reinterpret_cast<const float4*>(w)[2 * j + 1];
            H.h[0] = __float2half(v0.x); H.h[1] = __float2half(v0.y);
            H.h[2] = __float2half(v0.z); H.h[3] = __float2half(v0.w);
            H.h[4] = __float2half(v1.x); H.h[5] = __float2half(v1.y);
            H.h[6] = __float2half(v1.z); H.h[7] = __float2half(v1.w);
            reinterpret_cast<uint4*>(wh)[j] = H.u;
        }
    }
}

// ---------------- main GEMM kernel: TMA producer (tid0), mbarrier pipeline, 4 stages ----------------
// A/B tiles 128B-per-row, CU_TENSOR_MAP_SWIZZLE_128B == addr XOR ((c ^ (row&7))<<4)
__global__ void __launch_bounds__(256, 1) hmma_gemm(
    const __grid_constant__ CUtensorMap tma_a,
    const __grid_constant__ CUtensorMap tma_b,
    const float* __restrict__ bias,  // [N]
    float* __restrict__ out)         // [M, N]
{
    extern __shared__ __align__(1024) char smem[];
    const uint32_t sb = smem_u32(smem);
    const int tid = threadIdx.x;
    const int wid = tid >> 5;
    const int lane = tid & 31;
    const int warp_m = wid & 3;   // 0..3 -> 64-row slabs
    const int warp_n = wid >> 2;  // 0..1 -> 64-col slabs

    const uint32_t mb = sb + MBAR_OFF;        // full[s] at +16*s, empty[s] at +64+16*s
#define FULL_B(s)  (mb + 16 * (s))
#define EMPTY_B(s) (mb + 64 + 16 * (s))

    // supertile raster: GM m-tiles fastest, then n, then group
    const int bid = blockIdx.x;
    const int mt = (bid / (GM * NT2)) * GM + (bid % GM);
    const int nt = (bid / GM) % NT2;
    const int m0 = mt * BM;
    const int n0 = nt * BN;

    // init barriers: full counts 1 (tid0's expect_tx arrive); empty counts 8
    if (tid == 0) {
#pragma unroll
        for (int s = 0; s < NSTAGE; s++) {
            MBAR_INIT(FULL_B(s), 1);
            MBAR_INIT(EMPTY_B(s), 8);
        }
    }
    __syncthreads();   // once, for init visibility

    // TMA fill of one chunk: expect full stage bytes, then 2 loads
    auto tma_fill = [&](int s, int kt) {
        MBAR_EXPECT_TX(FULL_B(s), STAGE_BYTES);
        TMA_LOAD_2D(sb + s * STAGE_BYTES,           &tma_a, kt * BK, m0, FULL_B(s));
        TMA_LOAD_2D(sb + s * STAGE_BYTES + A_BYTES, &tma_b, kt * BK, n0, FULL_B(s));
    };

    // prologue: fill stages 0..2 (chunks 0..2)
    if (tid == 0) {
#pragma unroll
        for (int c = 0; c < NSTAGE - 1; c++) tma_fill(c, c);
    }

    float acc[4][8][4];
#pragma unroll
    for (int i = 0; i < 4; i++)
#pragma unroll
        for (int j = 0; j < 8; j++)
#pragma unroll
            for (int q = 0; q < 4; q++) acc[i][j][q] = 0.0f;

    for (int kt = 0; kt < KT2; kt++) {
        const int s = kt & 3;
        MBAR_WAIT(FULL_B(s), (kt >> 2) & 1);

        const uint32_t sA = sb + s * STAGE_BYTES;
        const uint32_t sB = sA + A_BYTES;

#pragma unroll
        for (int ks = 0; ks < 4; ks++) {   // 4 x k16 per BK=64 chunk
            uint32_t a[4][4];
#pragma unroll
            for (int mi = 0; mi < 4; mi++) {
                int row = warp_m * 64 + mi * 16 + (lane & 15);
                int chunk = ks * 2 + (lane >> 4);
                uint32_t addr = sA + row * 128 + ((chunk ^ (row & 7)) << 4);
                LDMATRIX_X4(a[mi][0], a[mi][1], a[mi][2], a[mi][3], addr);
            }
            uint32_t b[8][2];
#pragma unroll
            for (int p = 0; p < 4; p++) {
                int lane8 = lane & 7;
                int g = lane >> 3;
                int rowb = warp_n * 64 + p * 16 + ((g & 2) ? 8 : 0) + lane8;
                int chunk = ks * 2 + (g & 1);
                uint32_t addr = sB + rowb * 128 + ((chunk ^ (rowb & 7)) << 4);
                LDMATRIX_X4(b[2 * p][0], b[2 * p][1], b[2 * p + 1][0], b[2 * p + 1][1], addr);
            }
#pragma unroll
            for (int mi = 0; mi < 4; mi++)
#pragma unroll
                for (int ni = 0; ni < 8; ni++)
                    MMA_16816(acc[mi][ni], a[mi], b[ni]);
        }

        // done reading stage s: warp-elected arrive
        __syncwarp();
        if (lane == 0) MBAR_ARRIVE(EMPTY_B(s));

        // tid0 produces chunk kt+3 via TMA (engine-async; no per-thread loads)
        const int cp = kt + NSTAGE - 1;
        if (tid == 0 && cp < KT2) {
            const int sp = cp & 3;
            if (cp >= NSTAGE) MBAR_WAIT(EMPTY_B(sp), ((cp >> 2) + 1) & 1);
            tma_fill(sp, cp);
        }
    }

    // -------- epilogue: direct register -> gmem (float2), + bias --------
    float2 bv[8];
#pragma unroll
    for (int ni = 0; ni < 8; ni++) {
        int col = n0 + warp_n * 64 + ni * 8 + 2 * (lane & 3);
        bv[ni] = *reinterpret_cast<const float2*>(bias + col);
    }
#pragma unroll
    for (int mi = 0; mi < 4; mi++) {
        size_t r0 = (size_t)(m0 + warp_m * 64 + mi * 16 + (lane >> 2));
        size_t r1 = r0 + 8;
#pragma unroll
        for (int ni = 0; ni < 8; ni++) {
            int col = n0 + warp_n * 64 + ni * 8 + 2 * (lane & 3);
            float2 v0 = make_float2(acc[mi][ni][0] + bv[ni].x, acc[mi][ni][1] + bv[ni].y);
            float2 v1 = make_float2(acc[mi][ni][2] + bv[ni].x, acc[mi][ni][3] + bv[ni].y);
            *reinterpret_cast<float2*>(out + r0 * DIM_N + col) = v0;
            *reinterpret_cast<float2*>(out + r1 * DIM_N + col) = v1;
        }
    }
}

// ---------------- host launch ----------------
typedef CUresult (*tmap_encode_fn)(CUtensorMap*, CUtensorMapDataType, cuuint32_t, void*,
                                   const cuuint64_t*, const cuuint64_t*, const cuuint32_t*,
                                   const cuuint32_t*, CUtensorMapInterleave, CUtensorMapSwizzle,
                                   CUtensorMapL2promotion, CUtensorMapFloatOOBfill);

static bool encode_2d(tmap_encode_fn enc, CUtensorMap* map, void* ptr,
                      uint64_t d0, uint64_t d1, uint32_t b0, uint32_t b1) {
    cuuint64_t dims[2] = {d0, d1};
    cuuint64_t strides[1] = {d0 * 2};  // fp16 bytes
    cuuint32_t box[2] = {b0, b1};
    cuuint32_t es[2] = {1, 1};
    return enc(map, CU_TENSOR_MAP_DATA_TYPE_FLOAT16, 2, ptr, dims, strides, box, es,
               CU_TENSOR_MAP_INTERLEAVE_NONE, CU_TENSOR_MAP_SWIZZLE_128B,
               CU_TENSOR_MAP_L2_PROMOTION_L2_128B,
               CU_TENSOR_MAP_FLOAT_OOB_FILL_NONE) == CUDA_SUCCESS;
}

extern "C" void kernel_launch(void* const* d_in, const int* in_sizes, int n_in,
                              void* d_out, int out_size) {
    const float* x     = (const float*)d_in[0];
    const float* w     = (const float*)d_in[1];
    const float* scale = (const float*)d_in[2];
    const float* bias  = (const float*)d_in[3];
    float* out = (float*)d_out;

    void *p_xh = nullptr, *p_wh = nullptr;
    cudaGetSymbolAddress(&p_xh, g_x_h);
    cudaGetSymbolAddress(&p_wh, g_w_h);

    const int n8x = DIM_M * DIM_K / 8;
    const int n8w = (int)((size_t)DIM_N * DIM_K / 8);
    const int n8tot = n8x + n8w;
    const int cta = 256;
    int blocks = (n8tot + cta * 4 - 1) / (cta * 4);
    conv_all_f16<<<blocks, cta>>>(x, w, scale, (__half*)p_xh, (__half*)p_wh, n8x, n8tot);

    // TMA descriptors via runtime driver-entry-point (no -lcuda link needed)
    void* fn = nullptr;
    cudaDriverEntryPointQueryResult qr;
    cudaGetDriverEntryPointByVersion("cuTensorMapEncodeTiled", &fn, 12000,
                                     cudaEnableDefault, &qr);
    if (fn == nullptr) return;  // fail loudly (output stays poisoned)
    tmap_encode_fn enc = (tmap_encode_fn)fn;

    CUtensorMap tm_a, tm_b;
    if (!encode_2d(enc, &tm_a, p_xh, DIM_K, DIM_M, BK, BM)) return;
    if (!encode_2d(enc, &tm_b, p_wh, DIM_K, DIM_N, BK, BN)) return;

    cudaFuncSetAttribute(hmma_gemm, cudaFuncAttributeMaxDynamicSharedMemorySize, SMEM_TOTAL);
    hmma_gemm<<<MT2 * NT2, 256, SMEM_TOTAL>>>(tm_a, tm_b, bias, out);
}